// round 4
// baseline (speedup 1.0000x reference)
#include <cuda_runtime.h>
#include <cuda_bf16.h>
#include <cstdint>

// Problem constants (fixed shapes)
#define NIMG 28           // B*T pairs = 4*7
#define HW   4096         // 64*64
#define PP   441          // 21*21
#define NTOT (NIMG*HW)    // elements per displacement = 114688

// ---------------- device scratch (allowed: __device__ globals) ----------------
__device__ float g_cor[(size_t)NIMG * PP * HW];   // ~202 MB
__device__ float g_scale[PP];
__device__ float g_shift[PP];
__device__ float g_w2t[PP * 64];                  // [p][o], scale folded
__device__ float g_bias[64];

// ---------------- f32x2 helpers ----------------
typedef unsigned long long ull;
__device__ __forceinline__ ull f32x2_dup(float x) {
    ull r; asm("mov.b64 %0, {%1, %1};" : "=l"(r) : "f"(x)); return r;
}
__device__ __forceinline__ void f32x2_fma(ull& d, ull a, ull b) {
    asm("fma.rn.f32x2 %0, %1, %2, %0;" : "+l"(d) : "l"(a), "l"(b));
}
__device__ __forceinline__ float2 f32x2_unpack(ull v) {
    float2 r; asm("mov.b64 {%0, %1}, %2;" : "=f"(r.x), "=f"(r.y) : "l"(v)); return r;
}

// =======================================================================
// Kernel 1: correlation.
// cor[n, dy*21+dx, h, w] = sum_c f1[n,c,h,w] * f2[n,c, h+2dy-20, w+2dx-20]
// Grid: (4 row-tiles of 16, 28 n, 7 dy-groups of 3).  Block 256 = 16r x 16g,
// thread owns 4 consecutive w.  Channel chunks of 4 staged in smem.
// =======================================================================
#define RT   16
#define CCH  4
#define SC2  104   // f2 stage columns (global col -20..83)

__global__ void __launch_bounds__(256, 1) corr_kernel(const float* __restrict__ feats) {
    __shared__ float f1s[CCH][RT][64];
    __shared__ float f2s[CCH][RT][SC2];

    const int h0  = blockIdx.x * RT;
    const int n   = blockIdx.y;
    const int dyg = blockIdx.z;
    const int b   = n / 7, t = n % 7;

    const int tid = threadIdx.x;
    const int r   = tid >> 4;        // 0..15
    const int g   = tid & 15;        // 0..15 (w group of 4)

    const float* f1base = feats + ((size_t)(b * 8 + t)     ) * 64 * HW;
    const float* f2base = feats + ((size_t)(b * 8 + t + 1) ) * 64 * HW;

    for (int j = 0; j < 3; j++) {
        const int dy = dyg * 3 + j;
        const int d  = 2 * dy - 20;

        float4 acc[21];
#pragma unroll
        for (int px = 0; px < 21; px++) acc[px] = make_float4(0.f, 0.f, 0.f, 0.f);

        for (int cc = 0; cc < 16; cc++) {
            const int c0 = cc * CCH;
            __syncthreads();   // previous compute done before refill

            // ---- fill f1s: CCH*16*16 = 1024 float4, 4 per thread ----
#pragma unroll
            for (int it = 0; it < 4; it++) {
                int idx = tid + it * 256;
                int k  = idx & 15;
                int rr = (idx >> 4) & 15;
                int ci = idx >> 8;
                const float4 v = *(const float4*)(f1base + (size_t)(c0 + ci) * HW
                                                  + (h0 + rr) * 64 + 4 * k);
                *(float4*)&f1s[ci][rr][4 * k] = v;
            }

            // ---- fill f2s: CCH*16*26 = 1664 float4 slots ----
#pragma unroll
            for (int it = 0; it < 7; it++) {
                int idx = tid + it * 256;
                if (idx < CCH * RT * 26) {
                    int k  = idx % 26;
                    int rr = (idx / 26) % RT;
                    int ci = idx / (26 * RT);
                    int grow = h0 + rr + d;
                    int gcol = 4 * k - 20;
                    float4 v = make_float4(0.f, 0.f, 0.f, 0.f);
                    if ((unsigned)grow < 64u && (unsigned)gcol < 64u) {
                        v = *(const float4*)(f2base + (size_t)(c0 + ci) * HW
                                             + grow * 64 + gcol);
                    }
                    *(float4*)&f2s[ci][rr][4 * k] = v;
                }
            }
            __syncthreads();

            // ---- compute ----
#pragma unroll
            for (int ci = 0; ci < CCH; ci++) {
                const float4 f1v = *(const float4*)&f1s[ci][r][4 * g];
                const float* base = &f2s[ci][r][4 * g];
                float4 cur = *(const float4*)base;
#pragma unroll
                for (int i = 0; i <= 10; i++) {
                    // px = 2i : window rel cols 4i..4i+3 = cur
                    acc[2 * i].x += f1v.x * cur.x;
                    acc[2 * i].y += f1v.y * cur.y;
                    acc[2 * i].z += f1v.z * cur.z;
                    acc[2 * i].w += f1v.w * cur.w;
                    if (i < 10) {
                        const float4 nxt = *(const float4*)(base + 4 * (i + 1));
                        // px = 2i+1 : rel cols 4i+2..4i+5 = (cur.z,cur.w,nxt.x,nxt.y)
                        acc[2 * i + 1].x += f1v.x * cur.z;
                        acc[2 * i + 1].y += f1v.y * cur.w;
                        acc[2 * i + 1].z += f1v.z * nxt.x;
                        acc[2 * i + 1].w += f1v.w * nxt.y;
                        cur = nxt;
                    }
                }
            }
        }

        // ---- store 21 float4 ----
        float* dst0 = g_cor + ((size_t)n * PP + dy * 21) * HW + (h0 + r) * 64 + 4 * g;
#pragma unroll
        for (int px = 0; px < 21; px++) {
            *(float4*)(dst0 + (size_t)px * HW) = acc[px];
        }
    }
}

// =======================================================================
// Kernel 2: per-displacement batch stats -> scale/shift (BN folded)
// =======================================================================
__global__ void __launch_bounds__(256) stats_kernel(const float* __restrict__ gamma,
                                                    const float* __restrict__ beta) {
    const int p = blockIdx.x;
    const int tid = threadIdx.x;
    float s = 0.f, sq = 0.f;
    // 28 images * 1024 float4 each for this p
    for (int i = tid; i < NIMG * 1024; i += 256) {
        int n   = i >> 10;
        int hw4 = i & 1023;
        const float4 v = *(const float4*)(g_cor + ((size_t)n * PP + p) * HW + 4 * hw4);
        s  += v.x + v.y + v.z + v.w;
        sq += v.x * v.x + v.y * v.y + v.z * v.z + v.w * v.w;
    }
    // block reduce
    __shared__ float rs[8], rq[8];
#pragma unroll
    for (int o = 16; o > 0; o >>= 1) {
        s  += __shfl_down_sync(0xffffffffu, s, o);
        sq += __shfl_down_sync(0xffffffffu, sq, o);
    }
    if ((tid & 31) == 0) { rs[tid >> 5] = s; rq[tid >> 5] = sq; }
    __syncthreads();
    if (tid == 0) {
        float ts = 0.f, tq = 0.f;
#pragma unroll
        for (int i = 0; i < 8; i++) { ts += rs[i]; tq += rq[i]; }
        const float inv = 1.0f / (float)NTOT;
        float mean = ts * inv;
        float var  = tq * inv - mean * mean;
        float sc   = gamma[p] * rsqrtf(var + 1e-5f);
        g_scale[p] = sc;
        g_shift[p] = beta[p] - mean * sc;
    }
}

// =======================================================================
// Kernel 3: fold scale into weights (transposed) + bias
// =======================================================================
__global__ void __launch_bounds__(256) prep_kernel(const float* __restrict__ conv_w) {
    const int o = blockIdx.x;     // 0..63
    const int tid = threadIdx.x;
    float bsum = 0.f;
    for (int p = tid; p < PP; p += 256) {
        float w  = conv_w[o * PP + p];
        g_w2t[p * 64 + o] = w * g_scale[p];
        bsum += w * g_shift[p];
    }
    __shared__ float rb[8];
#pragma unroll
    for (int off = 16; off > 0; off >>= 1) bsum += __shfl_down_sync(0xffffffffu, bsum, off);
    if ((tid & 31) == 0) rb[tid >> 5] = bsum;
    __syncthreads();
    if (tid == 0) {
        float tb = 0.f;
#pragma unroll
        for (int i = 0; i < 8; i++) tb += rb[i];
        g_bias[o] = tb;
    }
}

// =======================================================================
// Kernel 4: GEMM  out[n,o,hw] = sum_p w2t[p][o] * cor[n,p,hw] + bias[o]
// Block tile: 64 o x 256 hw, thread 8o x (4+4) hw, f32x2 FMAs, K chunks of 8.
// =======================================================================
#define KC 8

__global__ void __launch_bounds__(256, 1) gemm_kernel(float* __restrict__ out) {
    __shared__ float cors[KC][256];
    __shared__ float ws[KC][64];

    const int hw0 = blockIdx.x * 256;
    const int n   = blockIdx.y;
    const int b   = n / 7, t = n % 7;
    const int fo  = b * 8 + t;

    const int tid = threadIdx.x;
    const int og  = tid >> 5;       // 0..7
    const int hwg = tid & 31;       // 0..31

    ull acc[8][4];
#pragma unroll
    for (int o = 0; o < 8; o++)
#pragma unroll
        for (int q = 0; q < 4; q++) acc[o][q] = 0ull;

    const float* corn = g_cor + (size_t)n * PP * HW;

    const int NK = (PP + KC - 1) / KC;   // 56
    for (int ch = 0; ch < NK; ch++) {
        const int k0 = ch * KC;
        __syncthreads();

        // stage cor: KC*256 floats = 512 float4, 2 per thread
#pragma unroll
        for (int it = 0; it < 2; it++) {
            int idx = tid + it * 256;
            int kk  = idx >> 6;
            int c4  = idx & 63;
            float4 v = make_float4(0.f, 0.f, 0.f, 0.f);
            if (k0 + kk < PP)
                v = *(const float4*)(corn + (size_t)(k0 + kk) * HW + hw0 + 4 * c4);
            *(float4*)&cors[kk][4 * c4] = v;
        }
        // stage w: KC*64 floats = 128 float4
        if (tid < 128) {
            int kk = tid >> 4;
            int c4 = tid & 15;
            float4 v = make_float4(0.f, 0.f, 0.f, 0.f);
            if (k0 + kk < PP)
                v = *(const float4*)(g_w2t + (size_t)(k0 + kk) * 64 + 4 * c4);
            *(float4*)&ws[kk][4 * c4] = v;
        }
        __syncthreads();

#pragma unroll
        for (int kk = 0; kk < KC; kk++) {
            // a-frag: 8 w values for this og (broadcast within warp)
            const float4 w0 = *(const float4*)&ws[kk][og * 8];
            const float4 w1 = *(const float4*)&ws[kk][og * 8 + 4];
            ull ad[8];
            ad[0] = f32x2_dup(w0.x); ad[1] = f32x2_dup(w0.y);
            ad[2] = f32x2_dup(w0.z); ad[3] = f32x2_dup(w0.w);
            ad[4] = f32x2_dup(w1.x); ad[5] = f32x2_dup(w1.y);
            ad[6] = f32x2_dup(w1.z); ad[7] = f32x2_dup(w1.w);
            // b-frag: two float4 halves, 128 apart
            const ulonglong2 b01 = *(const ulonglong2*)&cors[kk][hwg * 4];
            const ulonglong2 b23 = *(const ulonglong2*)&cors[kk][128 + hwg * 4];
#pragma unroll
            for (int o = 0; o < 8; o++) {
                f32x2_fma(acc[o][0], ad[o], b01.x);
                f32x2_fma(acc[o][1], ad[o], b01.y);
                f32x2_fma(acc[o][2], ad[o], b23.x);
                f32x2_fma(acc[o][3], ad[o], b23.y);
            }
        }
    }

    // epilogue: add bias, store
    float* outn = out + (size_t)fo * 64 * HW;
#pragma unroll
    for (int o = 0; o < 8; o++) {
        const int oo = og * 8 + o;
        const float bv = g_bias[oo];
        float2 p0 = f32x2_unpack(acc[o][0]);
        float2 p1 = f32x2_unpack(acc[o][1]);
        float2 p2 = f32x2_unpack(acc[o][2]);
        float2 p3 = f32x2_unpack(acc[o][3]);
        float* dst = outn + (size_t)oo * HW + hw0;
        *(float4*)(dst + hwg * 4)       = make_float4(p0.x + bv, p0.y + bv, p1.x + bv, p1.y + bv);
        *(float4*)(dst + 128 + hwg * 4) = make_float4(p2.x + bv, p2.y + bv, p3.x + bv, p3.y + bv);
    }
}

// =======================================================================
extern "C" void kernel_launch(void* const* d_in, const int* in_sizes, int n_in,
                              void* d_out, int out_size) {
    const float* feats  = (const float*)d_in[0];   // [4,8,64,64,64]
    const float* gamma  = (const float*)d_in[1];   // [441]
    const float* beta   = (const float*)d_in[2];   // [441]
    const float* conv_w = (const float*)d_in[3];   // [64,441]
    float* out = (float*)d_out;                    // [4,8,64,64,64]

    corr_kernel<<<dim3(4, 28, 7), 256>>>(feats);
    stats_kernel<<<PP, 256>>>(gamma, beta);
    prep_kernel<<<64, 256>>>(conv_w);
    gemm_kernel<<<dim3(16, 28), 256>>>(out);

    // zero frame t=7 for each batch
    const size_t frame = (size_t)64 * HW;
    for (int b = 0; b < 4; b++) {
        cudaMemsetAsync(out + ((size_t)(b * 8 + 7)) * frame, 0, frame * sizeof(float));
    }
}

// round 5
// speedup vs baseline: 1.3008x; 1.3008x over previous
#include <cuda_runtime.h>
#include <cuda_bf16.h>
#include <cuda_pipeline.h>
#include <cstdint>

// Problem constants (fixed shapes)
#define NIMG 28           // B*T pairs = 4*7
#define HW   4096         // 64*64
#define PP   441          // 21*21
#define NTOT (NIMG*HW)    // elements per displacement = 114688
#define KPAD 448          // padded K for GEMM

// ---------------- device scratch ----------------
__device__ float g_cor[(size_t)NIMG * PP * HW + 7 * HW];  // pad 7 rows for K=448 reads
__device__ float g_parts [PP * 112];
__device__ float g_partsq[PP * 112];
__device__ float g_scale[PP];
__device__ float g_shift[PP];
__device__ float g_w2t[KPAD * 64];                 // [p][o], scale folded, zero-padded
__device__ float g_bias[64];

// ---------------- f32x2 helpers ----------------
typedef unsigned long long ull;
__device__ __forceinline__ ull f32x2_dup(float x) {
    ull r; asm("mov.b64 %0, {%1, %1};" : "=l"(r) : "f"(x)); return r;
}
__device__ __forceinline__ ull f32x2_pack(float x, float y) {
    ull r; asm("mov.b64 %0, {%1, %2};" : "=l"(r) : "f"(x), "f"(y)); return r;
}
__device__ __forceinline__ void f32x2_fma(ull& d, ull a, ull b) {
    asm("fma.rn.f32x2 %0, %1, %2, %0;" : "+l"(d) : "l"(a), "l"(b));
}
__device__ __forceinline__ float2 f32x2_unpack(ull v) {
    float2 r; asm("mov.b64 {%0, %1}, %2;" : "=f"(r.x), "=f"(r.y) : "l"(v)); return r;
}

// =======================================================================
// Kernel 1: correlation + fused BN-stat partials.
// cor[n, dy*21+dx, h, w] = sum_c f1[n,c,h,w] * f2[n,c, h+2dy-20, w+2dx-20]
// Grid (4 htiles, 28 n, 21 dy).  Block 128 = 16 r x 8 g; thread owns 8 w.
// f2 rows staged in dynamic smem (row stride 108 floats => conflict-free),
// channel chunks of 4, cp.async double buffered.  All math is f32x2.
// =======================================================================
#define CCH 4
#define ROWF 108                       // smem floats per staged row
#define STAGEF (CCH * 16 * ROWF)       // 6912 floats per buffer
#define CORR_SMEM_BYTES (2 * STAGEF * 4)   // 55296

__global__ void __launch_bounds__(128, 2) corr_kernel(const float* __restrict__ feats) {
    extern __shared__ float sm[];
    const int h0 = blockIdx.x * 16;
    const int n  = blockIdx.y;
    const int dy = blockIdx.z;
    const int b  = n / 7, t = n % 7;
    const int d  = 2 * dy - 20;

    const int tid = threadIdx.x;
    const int r   = tid & 15;          // row in tile
    const int g   = tid >> 4;          // 0..7, owns w = 8g..8g+7

    const float* f1p    = feats + (size_t)(b * 8 + t) * 64 * HW + (h0 + r) * 64 + 8 * g;
    const float* f2base = feats + (size_t)(b * 8 + t + 1) * 64 * HW;

    // zero both stage buffers once (OOB rows/cols stay zero)
    for (int i = tid; i < 2 * STAGEF; i += 128) sm[i] = 0.f;
    __syncthreads();

    auto fill = [&](int s, int buf) {
        const int c0 = s * CCH;
        float* dstb = sm + buf * STAGEF;
#pragma unroll
        for (int it = 0; it < 8; it++) {
            int idx = tid + it * 128;           // < 1024
            int ci  = idx >> 8;
            int rr  = (idx >> 4) & 15;
            int k   = (idx & 15) + 5;           // valid float4 cols: scol 4k, gcol 4k-20
            int grow = h0 + rr + d;
            if ((unsigned)grow < 64u) {
                __pipeline_memcpy_async(dstb + (ci * 16 + rr) * ROWF + 4 * k,
                    f2base + (size_t)(c0 + ci) * HW + grow * 64 + (4 * k - 20), 16);
            }
        }
    };

    fill(0, 0);
    __pipeline_commit();

    ull acc[21][4];
#pragma unroll
    for (int px = 0; px < 21; px++)
#pragma unroll
        for (int q = 0; q < 4; q++) acc[px][q] = 0ull;

    for (int s = 0; s < 16; s++) {
        const int buf = s & 1;
        if (s + 1 < 16) { fill(s + 1, buf ^ 1); __pipeline_commit(); }
        if (s + 1 < 16) __pipeline_wait_prior(1); else __pipeline_wait_prior(0);
        __syncthreads();

        const int c0 = s * CCH;
        const float* f1c = f1p + (size_t)c0 * HW;
        const float* wb  = sm + buf * STAGEF + r * ROWF + 8 * g;

#pragma unroll
        for (int ci = 0; ci < CCH; ci++) {
            const float4 a  = *(const float4*)(f1c + (size_t)ci * HW);
            const float4 b4 = *(const float4*)(f1c + (size_t)ci * HW + 4);
            const ull p01 = f32x2_pack(a.x,  a.y);
            const ull p23 = f32x2_pack(a.z,  a.w);
            const ull p45 = f32x2_pack(b4.x, b4.y);
            const ull p67 = f32x2_pack(b4.z, b4.w);

            const float* w = wb + ci * (16 * ROWF);
            ull u0 = *(const ull*)(w);
            ull u1 = *(const ull*)(w + 2);
            ull u2 = *(const ull*)(w + 4);
            ull u3 = *(const ull*)(w + 6);
#pragma unroll
            for (int dx = 0; dx < 21; dx++) {
                f32x2_fma(acc[dx][0], p01, u0);
                f32x2_fma(acc[dx][1], p23, u1);
                f32x2_fma(acc[dx][2], p45, u2);
                f32x2_fma(acc[dx][3], p67, u3);
                if (dx < 20) {
                    u0 = u1; u1 = u2; u2 = u3;
                    u3 = *(const ull*)(w + 2 * dx + 8);
                }
            }
        }
        __syncthreads();   // all reads of buf done before it is refilled
    }

    // ---- store 21 x 8 floats ----
    float* dst0 = g_cor + ((size_t)n * PP + (size_t)dy * 21) * HW + (h0 + r) * 64 + 8 * g;
#pragma unroll
    for (int dx = 0; dx < 21; dx++) {
        *(ulonglong2*)(dst0 + (size_t)dx * HW)     = make_ulonglong2(acc[dx][0], acc[dx][1]);
        *(ulonglong2*)(dst0 + (size_t)dx * HW + 4) = make_ulonglong2(acc[dx][2], acc[dx][3]);
    }

    // ---- fused stat partials: per-p sum / sumsq over this block's 1024 px ----
    __syncthreads();   // smem free for reduction
#pragma unroll
    for (int dx = 0; dx < 21; dx++) {
        float s = 0.f, q = 0.f;
#pragma unroll
        for (int k = 0; k < 4; k++) {
            float2 v = f32x2_unpack(acc[dx][k]);
            s += v.x + v.y;
            q += v.x * v.x + v.y * v.y;
        }
        sm[dx * 128 + tid]        = s;
        sm[(21 + dx) * 128 + tid] = q;
    }
    __syncthreads();
    if (tid < 42) {
        float v = 0.f;
        const float* row = sm + tid * 128;
#pragma unroll 8
        for (int i = 0; i < 128; i++) v += row[i];
        const int px = (tid < 21) ? tid : tid - 21;
        const int p  = dy * 21 + px;
        const int bi = blockIdx.x * 28 + n;     // 0..111
        if (tid < 21) g_parts[p * 112 + bi] = v;
        else          g_partsq[p * 112 + bi] = v;
    }
}

// =======================================================================
// Kernel 2: finish stats -> scale/shift
// =======================================================================
__global__ void __launch_bounds__(448) stats2_kernel(const float* __restrict__ gamma,
                                                     const float* __restrict__ beta) {
    const int p = threadIdx.x;
    if (p >= PP) return;
    float s = 0.f, q = 0.f;
    const float* ps = g_parts  + p * 112;
    const float* pq = g_partsq + p * 112;
#pragma unroll 8
    for (int i = 0; i < 112; i++) { s += ps[i]; q += pq[i]; }
    const float inv = 1.0f / (float)NTOT;
    float mean = s * inv;
    float var  = q * inv - mean * mean;
    float sc   = gamma[p] * rsqrtf(var + 1e-5f);
    g_scale[p] = sc;
    g_shift[p] = beta[p] - mean * sc;
}

// =======================================================================
// Kernel 3: fold scale into transposed weights + bias, zero-pad K to 448
// =======================================================================
__global__ void __launch_bounds__(256) prep_kernel(const float* __restrict__ conv_w) {
    const int o = blockIdx.x;
    const int tid = threadIdx.x;
    float bsum = 0.f;
    for (int p = tid; p < PP; p += 256) {
        float w = conv_w[o * PP + p];
        g_w2t[p * 64 + o] = w * g_scale[p];
        bsum += w * g_shift[p];
    }
    if (tid < KPAD - PP) g_w2t[(PP + tid) * 64 + o] = 0.f;
    __shared__ float rb[8];
#pragma unroll
    for (int off = 16; off > 0; off >>= 1) bsum += __shfl_down_sync(0xffffffffu, bsum, off);
    if ((tid & 31) == 0) rb[tid >> 5] = bsum;
    __syncthreads();
    if (tid == 0) {
        float tb = 0.f;
#pragma unroll
        for (int i = 0; i < 8; i++) tb += rb[i];
        g_bias[o] = tb;
    }
}

// =======================================================================
// Kernel 4: GEMM  out[n,o,hw] = sum_p w2t[p][o]*cor[n,p,hw] + bias[o]
// Block: 64 o x 128 hw, 256 thr = 8 og x 32 hwg (warp == one og -> w broadcast).
// K padded to 448 = 28 chunks of 16, cp.async double buffered.
// =======================================================================
#define KC 16

__global__ void __launch_bounds__(256, 2) gemm_kernel(float* __restrict__ out) {
    __shared__ float cs[2][KC][128];
    __shared__ float ws[2][KC][64];

    const int hw0 = blockIdx.x * 128;
    const int n   = blockIdx.y;
    const int fo  = (n / 7) * 8 + (n % 7);

    const int tid = threadIdx.x;
    const int og  = tid >> 5;
    const int hwg = tid & 31;

    const float* corn = g_cor + (size_t)n * PP * HW;

    auto fill = [&](int s, int buf) {
        const int k0 = s * KC;
#pragma unroll
        for (int it = 0; it < 2; it++) {
            int idx = tid + it * 256;          // < 512 : 16 k-rows x 32 float4
            int kk  = idx >> 5;
            int c4  = idx & 31;
            __pipeline_memcpy_async(&cs[buf][kk][4 * c4],
                corn + (size_t)(k0 + kk) * HW + hw0 + 4 * c4, 16);
        }
        {
            int kk = tid >> 4;                 // 256 thr : 16 k-rows x 16 float4
            int c4 = tid & 15;
            __pipeline_memcpy_async(&ws[buf][kk][4 * c4],
                g_w2t + (size_t)(k0 + kk) * 64 + 4 * c4, 16);
        }
    };

    ull acc[8][2];
#pragma unroll
    for (int o = 0; o < 8; o++) { acc[o][0] = 0ull; acc[o][1] = 0ull; }

    fill(0, 0);
    __pipeline_commit();

    const int NS = KPAD / KC;   // 28
    for (int s = 0; s < NS; s++) {
        const int buf = s & 1;
        if (s + 1 < NS) { fill(s + 1, buf ^ 1); __pipeline_commit(); }
        if (s + 1 < NS) __pipeline_wait_prior(1); else __pipeline_wait_prior(0);
        __syncthreads();

#pragma unroll
        for (int kk = 0; kk < KC; kk++) {
            const float4 w0 = *(const float4*)&ws[buf][kk][og * 8];
            const float4 w1 = *(const float4*)&ws[buf][kk][og * 8 + 4];
            const ulonglong2 bb = *(const ulonglong2*)&cs[buf][kk][hwg * 4];
            ull ad[8];
            ad[0] = f32x2_dup(w0.x); ad[1] = f32x2_dup(w0.y);
            ad[2] = f32x2_dup(w0.z); ad[3] = f32x2_dup(w0.w);
            ad[4] = f32x2_dup(w1.x); ad[5] = f32x2_dup(w1.y);
            ad[6] = f32x2_dup(w1.z); ad[7] = f32x2_dup(w1.w);
#pragma unroll
            for (int o = 0; o < 8; o++) {
                f32x2_fma(acc[o][0], ad[o], bb.x);
                f32x2_fma(acc[o][1], ad[o], bb.y);
            }
        }
        __syncthreads();
    }

    float* outn = out + (size_t)fo * 64 * HW;
#pragma unroll
    for (int o = 0; o < 8; o++) {
        const int oo = og * 8 + o;
        const float bv = g_bias[oo];
        float2 p0 = f32x2_unpack(acc[o][0]);
        float2 p1 = f32x2_unpack(acc[o][1]);
        *(float4*)(outn + (size_t)oo * HW + hw0 + hwg * 4) =
            make_float4(p0.x + bv, p0.y + bv, p1.x + bv, p1.y + bv);
    }
}

// =======================================================================
extern "C" void kernel_launch(void* const* d_in, const int* in_sizes, int n_in,
                              void* d_out, int out_size) {
    const float* feats  = (const float*)d_in[0];   // [4,8,64,64,64]
    const float* gamma  = (const float*)d_in[1];   // [441]
    const float* beta   = (const float*)d_in[2];   // [441]
    const float* conv_w = (const float*)d_in[3];   // [64,441]
    float* out = (float*)d_out;                    // [4,8,64,64,64]

    cudaFuncSetAttribute(corr_kernel, cudaFuncAttributeMaxDynamicSharedMemorySize,
                         CORR_SMEM_BYTES);

    corr_kernel<<<dim3(4, 28, 21), 128, CORR_SMEM_BYTES>>>(feats);
    stats2_kernel<<<1, 448>>>(gamma, beta);
    prep_kernel<<<64, 256>>>(conv_w);
    gemm_kernel<<<dim3(32, 28), 256>>>(out);

    const size_t frame = (size_t)64 * HW;
    for (int b = 0; b < 4; b++) {
        cudaMemsetAsync(out + ((size_t)(b * 8 + 7)) * frame, 0, frame * sizeof(float));
    }
}